// round 2
// baseline (speedup 1.0000x reference)
#include <cuda_runtime.h>
#include <cstdint>

#define BSZ   2048
#define NAG   32
#define NROWS (BSZ*NAG)     // 65536
#define IND   256
#define HID   256
#define NHD   4
#define HDIM  16
#define CVD   16
#define QKVG_N 196          // 64 q + 64 k + 64 v + 4 g
#define PIN_D 320           // 256 h + 64 gated messages
#define NACT  20
#define TOPK_K 8
#define NEGV  (-1e10f)

// ---------------- scratch (device globals; no allocation allowed) ----------
// g_X   : relu(fc1) [65536,256]; later reused for QKVG [65536,196]
// g_GI  : GRU input gates [65536,768]; later reused for PH [65536,256]
__device__ float g_X   [(size_t)NROWS * HID];
__device__ float g_GI  [(size_t)NROWS * 768];
__device__ float g_GH  [(size_t)NROWS * 768];
__device__ float g_PIN [(size_t)NROWS * PIN_D];   // [h | gated]
__device__ float g_Wp  [QKVG_N * HID];
__device__ float g_bp  [QKVG_N];

// ---------------- generic SGEMM: C[M,N] = A[M,K] @ B[N,K]^T + bias ---------
#define GBM 128
#define GBN 128
#define GBK 16

template<bool RELU>
__global__ void __launch_bounds__(256)
sgemm_bias(const float* __restrict__ A, int lda,
           const float* __restrict__ B,          // [N,K] row-major
           const float* __restrict__ bias,
           float* __restrict__ C, int ldc,
           int N, int K)
{
    __shared__ float As[GBK][GBM + 1];
    __shared__ float Bs[GBK][GBN + 1];

    const int tid = threadIdx.x;
    const int tn  = tid & 15;
    const int tm  = tid >> 4;
    const int m0  = blockIdx.y * GBM;
    const int n0  = blockIdx.x * GBN;

    float acc[8][8];
#pragma unroll
    for (int i = 0; i < 8; i++)
#pragma unroll
        for (int j = 0; j < 8; j++) acc[i][j] = 0.f;

    for (int k0 = 0; k0 < K; k0 += GBK) {
#pragma unroll
        for (int it = 0; it < 2; it++) {
            int f  = it * 256 + tid;           // 0..511 float4 slots
            int r  = f >> 2;                   // 0..127 row within tile
            int kk = (f & 3) * 4;              // 0,4,8,12
            float4 av = *(const float4*)(A + (size_t)(m0 + r) * lda + k0 + kk);
            As[kk + 0][r] = av.x; As[kk + 1][r] = av.y;
            As[kk + 2][r] = av.z; As[kk + 3][r] = av.w;
            float4 bv = make_float4(0.f, 0.f, 0.f, 0.f);
            if (n0 + r < N)
                bv = *(const float4*)(B + (size_t)(n0 + r) * K + k0 + kk);
            Bs[kk + 0][r] = bv.x; Bs[kk + 1][r] = bv.y;
            Bs[kk + 2][r] = bv.z; Bs[kk + 3][r] = bv.w;
        }
        __syncthreads();

#pragma unroll
        for (int kk = 0; kk < GBK; kk++) {
            float ra[8], rb[8];
#pragma unroll
            for (int i = 0; i < 8; i++) ra[i] = As[kk][tm * 8 + i];
#pragma unroll
            for (int j = 0; j < 8; j++) rb[j] = Bs[kk][tn * 8 + j];
#pragma unroll
            for (int i = 0; i < 8; i++)
#pragma unroll
                for (int j = 0; j < 8; j++)
                    acc[i][j] += ra[i] * rb[j];
        }
        __syncthreads();
    }

#pragma unroll
    for (int i = 0; i < 8; i++) {
        int m = m0 + tm * 8 + i;
#pragma unroll
        for (int j = 0; j < 8; j++) {
            int n = n0 + tn * 8 + j;
            if (n < N) {
                float v = acc[i][j] + bias[n];
                if (RELU) v = fmaxf(v, 0.f);
                C[(size_t)m * ldc + n] = v;
            }
        }
    }
}

// ---------------- GRU elementwise --------------------------------------------
__global__ void gru_kernel(const float* __restrict__ h_in,
                           float* __restrict__ h_out_tail)
{
    int idx = blockIdx.x * blockDim.x + threadIdx.x;
    if (idx >= NROWS * HID) return;
    int row = idx >> 8;
    int j   = idx & 255;
    size_t base = (size_t)row * 768;
    float gir = g_GI[base + j],       ghr = g_GH[base + j];
    float giz = g_GI[base + 256 + j], ghz = g_GH[base + 256 + j];
    float gin = g_GI[base + 512 + j], ghn = g_GH[base + 512 + j];
    float hp = h_in[idx];
    float r = 1.f / (1.f + __expf(-(gir + ghr)));
    float z = 1.f / (1.f + __expf(-(giz + ghz)));
    float n = tanhf(gin + r * ghn);
    float h = (1.f - z) * n + z * hp;
    g_PIN[(size_t)row * PIN_D + j] = h;
    h_out_tail[idx] = h;
}

// ---------------- pack q/k/v/g weights into one [196,256] matrix -------------
__global__ void pack_qkvg(const float* __restrict__ qw, const float* __restrict__ qb,
                          const float* __restrict__ kw, const float* __restrict__ kb,
                          const float* __restrict__ vw, const float* __restrict__ vb,
                          const float* __restrict__ gw, const float* __restrict__ gb)
{
    int n = blockIdx.x;                 // 0..195
    const float* src; const float* sb; int r;
    if      (n < 64)  { src = qw; sb = qb; r = n;       }
    else if (n < 128) { src = kw; sb = kb; r = n - 64;  }
    else if (n < 192) { src = vw; sb = vb; r = n - 128; }
    else              { src = gw; sb = gb; r = n - 192; }
    for (int k = threadIdx.x; k < HID; k += blockDim.x)
        g_Wp[n * HID + k] = src[r * HID + k];
    if (threadIdx.x == 0) g_bp[n] = sb[r];
}

// ---------------- attention per batch element --------------------------------
// QKVG lives in g_X (reused scratch).
__global__ void __launch_bounds__(256) attn_kernel()
{
    __shared__ float sq[NAG][NHD * HDIM];   // 32x64
    __shared__ float sk[NAG][NHD * HDIM];
    __shared__ float sv[NAG][NHD * CVD];
    __shared__ float sg[NAG][NHD];
    __shared__ float ss[NAG][NHD][NAG];     // scores -> alpha

    int b   = blockIdx.x;
    int tid = threadIdx.x;

    // load q/k/v/g for all 32 agents
    for (int idx = tid; idx < NAG * QKVG_N; idx += 256) {
        int a = idx / QKVG_N, c = idx % QKVG_N;
        float v = g_X[((size_t)(b * NAG + a)) * QKVG_N + c];
        if      (c < 64)  sq[a][c]       = v;
        else if (c < 128) sk[a][c - 64]  = v;
        else if (c < 192) sv[a][c - 128] = v;
        else              sg[a][c - 192] = v;
    }
    __syncthreads();

    // scores [q][h][k], diag masked
    for (int idx = tid; idx < NAG * NHD * NAG; idx += 256) {
        int qa = idx >> 7;
        int h  = (idx >> 5) & 3;
        int ka = idx & 31;
        float s;
        if (qa == ka) s = NEGV;
        else {
            s = 0.f;
#pragma unroll
            for (int d = 0; d < HDIM; d++)
                s += sq[qa][h * HDIM + d] * sk[ka][h * HDIM + d];
            s *= 0.25f;   // 1/sqrt(16)
        }
        ss[qa][h][ka] = s;
    }
    __syncthreads();

    // per (q,h): top-8 (value desc, lowest-index tie-break) then softmax
    if (tid < NAG * NHD) {
        int qa = tid >> 2, h = tid & 3;
        float* s = ss[qa][h];
        unsigned kept = 0u;
        float m = -3e38f;
#pragma unroll
        for (int t = 0; t < TOPK_K; t++) {
            float best = -3e38f; int bi = 0;
            for (int k = 0; k < NAG; k++)
                if (!((kept >> k) & 1u) && s[k] > best) { best = s[k]; bi = k; }
            kept |= 1u << bi;
            if (t == 0) m = best;
        }
        float denom = 0.f;
        for (int k = 0; k < NAG; k++) {
            float e = ((kept >> k) & 1u) ? __expf(s[k] - m) : 0.f;
            s[k] = e;
            denom += e;
        }
        float inv = 1.f / denom;
        for (int k = 0; k < NAG; k++) s[k] *= inv;
    }
    __syncthreads();

    // messages * gate -> PIN cols 256..319
    for (int idx = tid; idx < NAG * NHD * CVD; idx += 256) {
        int qa = idx >> 6;
        int h  = (idx >> 4) & 3;
        int c  = idx & 15;
        float acc = 0.f;
#pragma unroll
        for (int ka = 0; ka < NAG; ka++)
            acc += ss[qa][h][ka] * sv[ka][h * CVD + c];
        float gate = 1.f / (1.f + __expf(-sg[qa][h]));
        g_PIN[((size_t)(b * NAG + qa)) * PIN_D + HID + h * CVD + c] = acc * gate;
    }
}

// ---------------- launch ------------------------------------------------------
extern "C" void kernel_launch(void* const* d_in, const int* in_sizes, int n_in,
                              void* d_out, int out_size)
{
    const float* inputs   = (const float*)d_in[0];
    const float* hidden   = (const float*)d_in[1];
    const float* fc1_w    = (const float*)d_in[2];
    const float* fc1_b    = (const float*)d_in[3];
    const float* gru_w_ih = (const float*)d_in[4];
    const float* gru_w_hh = (const float*)d_in[5];
    const float* gru_b_ih = (const float*)d_in[6];
    const float* gru_b_hh = (const float*)d_in[7];
    const float* q_w = (const float*)d_in[8];
    const float* q_b = (const float*)d_in[9];
    const float* k_w = (const float*)d_in[10];
    const float* k_b = (const float*)d_in[11];
    const float* v_w = (const float*)d_in[12];
    const float* v_b = (const float*)d_in[13];
    const float* g_w = (const float*)d_in[14];
    const float* g_b = (const float*)d_in[15];
    const float* p1_w = (const float*)d_in[16];
    const float* p1_b = (const float*)d_in[17];
    const float* p2_w = (const float*)d_in[18];
    const float* p2_b = (const float*)d_in[19];

    float* out    = (float*)d_out;
    float* logits = out;                                // [65536,20]
    float* h_out  = out + (size_t)NROWS * NACT;         // [65536,256]

    float *X, *GI, *GH, *PIN, *Wp, *bp;
    cudaGetSymbolAddress((void**)&X,    g_X);
    cudaGetSymbolAddress((void**)&GI,   g_GI);
    cudaGetSymbolAddress((void**)&GH,   g_GH);
    cudaGetSymbolAddress((void**)&PIN,  g_PIN);
    cudaGetSymbolAddress((void**)&Wp,   g_Wp);
    cudaGetSymbolAddress((void**)&bp,   g_bp);
    float* QKVG = X;    // reuse: X dead after GI GEMM
    float* PH   = GI;   // reuse: GI dead after GRU

    const dim3 blk(256);
    const int gm = NROWS / GBM;   // 512

    // 1. X = relu(inputs @ fc1_w^T + fc1_b)
    sgemm_bias<true ><<<dim3(HID / GBN, gm), blk>>>(inputs, IND, fc1_w, fc1_b, X, HID, HID, IND);
    // 2. GI = X @ W_ih^T + b_ih
    sgemm_bias<false><<<dim3(768 / GBN, gm), blk>>>(X, HID, gru_w_ih, gru_b_ih, GI, 768, 768, HID);
    // 3. GH = hidden @ W_hh^T + b_hh
    sgemm_bias<false><<<dim3(768 / GBN, gm), blk>>>(hidden, HID, gru_w_hh, gru_b_hh, GH, 768, 768, HID);
    // 4. GRU -> h (into PIN[:, :256] and output tail)
    gru_kernel<<<(NROWS * HID) / 256, blk>>>(hidden, h_out);
    // 5. pack q/k/v/g weights
    pack_qkvg<<<QKVG_N, blk>>>(q_w, q_b, k_w, k_b, v_w, v_b, g_w, g_b);
    // 6. QKVG = h @ Wp^T + bp   (A = PIN with lda=320, K=256) -> into g_X
    sgemm_bias<false><<<dim3((QKVG_N + GBN - 1) / GBN, gm), blk>>>(PIN, PIN_D, Wp, bp, QKVG, QKVG_N, QKVG_N, HID);
    // 7. sparse attention -> PIN[:, 256:320]
    attn_kernel<<<BSZ, blk>>>();
    // 8. PH = relu(PIN @ p1_w^T + p1_b)   (K=320) -> into g_GI
    sgemm_bias<true ><<<dim3(HID / GBN, gm), blk>>>(PIN, PIN_D, p1_w, p1_b, PH, HID, HID, PIN_D);
    // 9. logits = PH @ p2_w^T + p2_b  (N=20, straight into d_out)
    sgemm_bias<false><<<dim3(1, gm), blk>>>(PH, HID, p2_w, p2_b, logits, NACT, NACT, HID);
}

// round 15
// speedup vs baseline: 1.2579x; 1.2579x over previous
#include <cuda_runtime.h>
#include <cstdint>

#define BSZ   2048
#define NAG   32
#define NROWS (BSZ*NAG)     // 65536
#define IND   256
#define HID   256
#define NHD   4
#define HDIM  16
#define CVD   16
#define QKVG_N 196
#define PIN_D 320
#define NACT  20
#define TOPK_K 8
#define NEGV  (-1e10f)

// ---------------- scratch ----------------
__device__ float g_X   [(size_t)NROWS * HID];     // relu(fc1); reused as QKVG
__device__ float g_GI  [(size_t)NROWS * 768];     // reused as PH
__device__ float g_GH  [(size_t)NROWS * 768];
__device__ float g_PIN [(size_t)NROWS * PIN_D];
__device__ float g_Wp  [QKVG_N * HID];
__device__ float g_bp  [QKVG_N];

// ---------------- mma.sync tf32 helpers (base-target sm_80+) ----------------
__device__ __forceinline__ uint32_t f2tf32(float x) {
    uint32_t r;
    asm("cvt.rna.tf32.f32 %0, %1;" : "=r"(r) : "f"(x));
    return r;
}
__device__ __forceinline__ void mma_tf32(float* c, const uint32_t* a, const uint32_t* b) {
    asm volatile("mma.sync.aligned.m16n8k8.row.col.f32.tf32.tf32.f32 "
                 "{%0,%1,%2,%3}, {%4,%5,%6,%7}, {%8,%9}, {%0,%1,%2,%3};"
                 : "+f"(c[0]), "+f"(c[1]), "+f"(c[2]), "+f"(c[3])
                 : "r"(a[0]), "r"(a[1]), "r"(a[2]), "r"(a[3]),
                   "r"(b[0]), "r"(b[1]));
}

// ---------------- split-tf32 HMMA GEMM: C = A[M,K] @ B[N,K]^T + bias --------
// Full-fp32 accuracy via 3-term tf32 emulation: a=ah+al, b=bh+bl,
// acc += ah*bh + ah*bl + al*bh  (al*bl ~2^-22, neglected).
// CTA: 256 thr, tile 128(M) x 128(N), K-chunks of 32.
// Warp grid 4(M) x 2(N); warp tile 32 x 64 = 2 m-tiles x 8 n-tiles m16n8k8.
// SMEM (48 KB static exactly):
//   As_hi/As_lo: fragment-permuted tf32 [kb][tm][lane][reg]  (16 KB each)
//   Bs: fragment-permuted raw f32 [kb][nt][lane][reg]        (16 KB), split at use.
// Fragment maps (validated in R11 by tf32-level rel_err):
//   A: a0=(g,c) a1=(g+8,c) a2=(g,c+4) a3=(g+8,c+4); lane = g*4+c
//   B: b0=(k=c, n=g) b1=(k=c+4, n=g)
//   C: c0=(g,2c) c1=(g,2c+1) c2=(g+8,2c) c3=(g+8,2c+1)
template<bool RELU>
__global__ void __launch_bounds__(256, 2)
hmma_gemm(const float* __restrict__ A, int lda,
          const float* __restrict__ B,            // [N,K] row-major
          const float* __restrict__ bias,
          float* __restrict__ C, int ldc,
          int Nfull, int K)
{
    __shared__ uint32_t As_hi[4 * 8 * 32 * 4];   // 16 KB
    __shared__ uint32_t As_lo[4 * 8 * 32 * 4];   // 16 KB
    __shared__ uint32_t Bs   [4 * 16 * 32 * 2];  // 16 KB (raw f32 bits)

    const int tid  = threadIdx.x;
    const int wid  = tid >> 5;
    const int lane = tid & 31;
    const int wm   = wid >> 1;       // 0..3  (M)
    const int wn   = wid & 1;        // 0..1  (N)
    const int m0   = blockIdx.y * 128;
    const int n0   = blockIdx.x * 128;

    float acc[2][8][4];
#pragma unroll
    for (int mt = 0; mt < 2; mt++)
#pragma unroll
        for (int j = 0; j < 8; j++)
#pragma unroll
            for (int r = 0; r < 4; r++) acc[mt][j][r] = 0.f;

    const int nkc = K >> 5;   // chunks of 32 (all K here are multiples of 32)

    for (int ch = 0; ch < nkc; ch++) {
        const int k0 = ch << 5;
        __syncthreads();
        // ---- cooperative load: A split hi/lo, B raw ----
#pragma unroll
        for (int it = 0; it < 4; it++) {
            int slot = it * 256 + tid;           // 0..1023
            int row  = slot >> 3;                // 0..127
            int k    = (slot & 7) << 2;          // 0,4,..,28
            int kb   = k >> 3;                   // 0..3
            int chh  = (k >> 2) & 1;             // hi half of k8 group
            // A (m0+row, k0+k..+3): split into tf32 hi + lo
            {
                float4 av = *(const float4*)(A + (size_t)(m0 + row) * lda + k0 + k);
                int tm  = row >> 4;
                int g   = row & 7;
                int hi  = (row >> 3) & 1;
                int reg = hi + 2 * chh;
                int base = ((kb * 8 + tm) * 32) * 4 + reg;
                float fv[4] = {av.x, av.y, av.z, av.w};
#pragma unroll
                for (int e = 0; e < 4; e++) {
                    uint32_t hb = f2tf32(fv[e]);
                    As_hi[base + (g * 4 + e) * 4] = hb;
                    As_lo[base + (g * 4 + e) * 4] = f2tf32(fv[e] - __uint_as_float(hb));
                }
            }
            // B (n0+row, k0+k..+3): raw f32 bits
            {
                float4 bv = make_float4(0.f, 0.f, 0.f, 0.f);
                if (n0 + row < Nfull)
                    bv = *(const float4*)(B + (size_t)(n0 + row) * K + k0 + k);
                int nt  = row >> 3;
                int g   = row & 7;
                int base = ((kb * 16 + nt) * 32) * 2 + chh;
                Bs[base + (g * 4 + 0) * 2] = __float_as_uint(bv.x);
                Bs[base + (g * 4 + 1) * 2] = __float_as_uint(bv.y);
                Bs[base + (g * 4 + 2) * 2] = __float_as_uint(bv.z);
                Bs[base + (g * 4 + 3) * 2] = __float_as_uint(bv.w);
            }
        }
        __syncthreads();
        // ---- 4 k-steps of m16n8k8, 3-term split ----
#pragma unroll
        for (int kb = 0; kb < 4; kb++) {
            uint32_t ah[2][4], al[2][4];
#pragma unroll
            for (int mt = 0; mt < 2; mt++) {
                int off = ((kb * 8 + wm * 2 + mt) * 32 + lane) * 4;
                uint4 vh = *(const uint4*)(As_hi + off);
                ah[mt][0] = vh.x; ah[mt][1] = vh.y; ah[mt][2] = vh.z; ah[mt][3] = vh.w;
                uint4 vl = *(const uint4*)(As_lo + off);
                al[mt][0] = vl.x; al[mt][1] = vl.y; al[mt][2] = vl.z; al[mt][3] = vl.w;
            }
#pragma unroll
            for (int j = 0; j < 8; j++) {
                uint2 braw = *(const uint2*)(Bs + ((kb * 16 + wn * 8 + j) * 32 + lane) * 2);
                float b0 = __uint_as_float(braw.x);
                float b1 = __uint_as_float(braw.y);
                uint32_t bh[2], bl[2];
                bh[0] = f2tf32(b0); bl[0] = f2tf32(b0 - __uint_as_float(bh[0]));
                bh[1] = f2tf32(b1); bl[1] = f2tf32(b1 - __uint_as_float(bh[1]));
#pragma unroll
                for (int mt = 0; mt < 2; mt++) {
                    mma_tf32(acc[mt][j], ah[mt], bh);
                    mma_tf32(acc[mt][j], ah[mt], bl);
                    mma_tf32(acc[mt][j], al[mt], bh);
                }
            }
        }
    }

    // ---- epilogue: bias (+relu), direct float2 stores ----
    const int g = lane >> 2;
    const int c = lane & 3;
#pragma unroll
    for (int mt = 0; mt < 2; mt++) {
#pragma unroll
        for (int j = 0; j < 8; j++) {
            int col = n0 + wn * 64 + j * 8 + c * 2;
            if (col >= Nfull) continue;
            float b0 = __ldg(bias + col);
            float b1 = __ldg(bias + col + 1);
            int r0 = m0 + wm * 32 + mt * 16 + g;
            float v0 = acc[mt][j][0] + b0;
            float v1 = acc[mt][j][1] + b1;
            float v2 = acc[mt][j][2] + b0;
            float v3 = acc[mt][j][3] + b1;
            if (RELU) {
                v0 = fmaxf(v0, 0.f); v1 = fmaxf(v1, 0.f);
                v2 = fmaxf(v2, 0.f); v3 = fmaxf(v3, 0.f);
            }
            *(float2*)(C + (size_t)r0 * ldc + col)       = make_float2(v0, v1);
            *(float2*)(C + (size_t)(r0 + 8) * ldc + col) = make_float2(v2, v3);
        }
    }
}

// ---------------- GRU elementwise ----------------
__global__ void gru_kernel(const float* __restrict__ h_in,
                           float* __restrict__ h_out_tail)
{
    int idx = blockIdx.x * blockDim.x + threadIdx.x;
    if (idx >= NROWS * HID) return;
    int row = idx >> 8;
    int j   = idx & 255;
    size_t base = (size_t)row * 768;
    float gir = g_GI[base + j],       ghr = g_GH[base + j];
    float giz = g_GI[base + 256 + j], ghz = g_GH[base + 256 + j];
    float gin = g_GI[base + 512 + j], ghn = g_GH[base + 512 + j];
    float hp = h_in[idx];
    float r = 1.f / (1.f + __expf(-(gir + ghr)));
    float z = 1.f / (1.f + __expf(-(giz + ghz)));
    float n = tanhf(gin + r * ghn);
    float h = (1.f - z) * n + z * hp;
    g_PIN[(size_t)row * PIN_D + j] = h;
    h_out_tail[idx] = h;
}

// ---------------- pack q/k/v/g weights ----------------
__global__ void pack_qkvg(const float* __restrict__ qw, const float* __restrict__ qb,
                          const float* __restrict__ kw, const float* __restrict__ kb,
                          const float* __restrict__ vw, const float* __restrict__ vb,
                          const float* __restrict__ gw, const float* __restrict__ gb)
{
    int n = blockIdx.x;
    const float* src; const float* sb; int r;
    if      (n < 64)  { src = qw; sb = qb; r = n;       }
    else if (n < 128) { src = kw; sb = kb; r = n - 64;  }
    else if (n < 192) { src = vw; sb = vb; r = n - 128; }
    else              { src = gw; sb = gb; r = n - 192; }
    for (int k = threadIdx.x; k < HID; k += blockDim.x)
        g_Wp[n * HID + k] = src[r * HID + k];
    if (threadIdx.x == 0) g_bp[n] = sb[r];
}

// ---------------- attention per batch element ----------------
__global__ void __launch_bounds__(256) attn_kernel()
{
    __shared__ float sq[NAG][NHD * HDIM];
    __shared__ float sk[NAG][NHD * HDIM];
    __shared__ float sv[NAG][NHD * CVD];
    __shared__ float sg[NAG][NHD];
    __shared__ float ss[NAG][NHD][NAG];

    int b   = blockIdx.x;
    int tid = threadIdx.x;

    for (int idx = tid; idx < NAG * QKVG_N; idx += 256) {
        int a = idx / QKVG_N, c = idx % QKVG_N;
        float v = g_X[((size_t)(b * NAG + a)) * QKVG_N + c];
        if      (c < 64)  sq[a][c]       = v;
        else if (c < 128) sk[a][c - 64]  = v;
        else if (c < 192) sv[a][c - 128] = v;
        else              sg[a][c - 192] = v;
    }
    __syncthreads();

    for (int idx = tid; idx < NAG * NHD * NAG; idx += 256) {
        int qa = idx >> 7;
        int h  = (idx >> 5) & 3;
        int ka = idx & 31;
        float s;
        if (qa == ka) s = NEGV;
        else {
            s = 0.f;
#pragma unroll
            for (int d = 0; d < HDIM; d++)
                s += sq[qa][h * HDIM + d] * sk[ka][h * HDIM + d];
            s *= 0.25f;
        }
        ss[qa][h][ka] = s;
    }
    __syncthreads();

    if (tid < NAG * NHD) {
        int qa = tid >> 2, h = tid & 3;
        float* s = ss[qa][h];
        unsigned kept = 0u;
        float m = -3e38f;
#pragma unroll
        for (int t = 0; t < TOPK_K; t++) {
            float best = -3e38f; int bi = 0;
            for (int k = 0; k < NAG; k++)
                if (!((kept >> k) & 1u) && s[k] > best) { best = s[k]; bi = k; }
            kept |= 1u << bi;
            if (t == 0) m = best;
        }
        float denom = 0.f;
        for (int k = 0; k < NAG; k++) {
            float e = ((kept >> k) & 1u) ? __expf(s[k] - m) : 0.f;
            s[k] = e;
            denom += e;
        }
        float inv = 1.f / denom;
        for (int k = 0; k < NAG; k++) s[k] *= inv;
    }
    __syncthreads();

    for (int idx = tid; idx < NAG * NHD * CVD; idx += 256) {
        int qa = idx >> 6;
        int h  = (idx >> 4) & 3;
        int c  = idx & 15;
        float acc = 0.f;
#pragma unroll
        for (int ka = 0; ka < NAG; ka++)
            acc += ss[qa][h][ka] * sv[ka][h * CVD + c];
        float gate = 1.f / (1.f + __expf(-sg[qa][h]));
        g_PIN[((size_t)(b * NAG + qa)) * PIN_D + HID + h * CVD + c] = acc * gate;
    }
}

// ---------------- launch ----------------
extern "C" void kernel_launch(void* const* d_in, const int* in_sizes, int n_in,
                              void* d_out, int out_size)
{
    const float* inputs   = (const float*)d_in[0];
    const float* hidden   = (const float*)d_in[1];
    const float* fc1_w    = (const float*)d_in[2];
    const float* fc1_b    = (const float*)d_in[3];
    const float* gru_w_ih = (const float*)d_in[4];
    const float* gru_w_hh = (const float*)d_in[5];
    const float* gru_b_ih = (const float*)d_in[6];
    const float* gru_b_hh = (const float*)d_in[7];
    const float* q_w = (const float*)d_in[8];
    const float* q_b = (const float*)d_in[9];
    const float* k_w = (const float*)d_in[10];
    const float* k_b = (const float*)d_in[11];
    const float* v_w = (const float*)d_in[12];
    const float* v_b = (const float*)d_in[13];
    const float* g_w = (const float*)d_in[14];
    const float* g_b = (const float*)d_in[15];
    const float* p1_w = (const float*)d_in[16];
    const float* p1_b = (const float*)d_in[17];
    const float* p2_w = (const float*)d_in[18];
    const float* p2_b = (const float*)d_in[19];

    float* out    = (float*)d_out;
    float* logits = out;
    float* h_out  = out + (size_t)NROWS * NACT;

    float *X, *GI, *GH, *PIN, *Wp, *bp;
    cudaGetSymbolAddress((void**)&X,    g_X);
    cudaGetSymbolAddress((void**)&GI,   g_GI);
    cudaGetSymbolAddress((void**)&GH,   g_GH);
    cudaGetSymbolAddress((void**)&PIN,  g_PIN);
    cudaGetSymbolAddress((void**)&Wp,   g_Wp);
    cudaGetSymbolAddress((void**)&bp,   g_bp);
    float* QKVG = X;
    float* PH   = GI;

    const dim3 blk(256);
    const int gm = NROWS / 128;   // 512

    // 1. X = relu(inputs @ fc1_w^T + fc1_b)
    hmma_gemm<true ><<<dim3(2, gm), blk>>>(inputs, IND, fc1_w, fc1_b, X, HID, HID, IND);
    // 2. GI = X @ W_ih^T + b_ih
    hmma_gemm<false><<<dim3(6, gm), blk>>>(X, HID, gru_w_ih, gru_b_ih, GI, 768, 768, HID);
    // 3. GH = hidden @ W_hh^T + b_hh
    hmma_gemm<false><<<dim3(6, gm), blk>>>(hidden, HID, gru_w_hh, gru_b_hh, GH, 768, 768, HID);
    // 4. GRU -> h (PIN[:, :256] + output tail)
    gru_kernel<<<(NROWS * HID) / 256, blk>>>(hidden, h_out);
    // 5. pack q/k/v/g weights
    pack_qkvg<<<QKVG_N, blk>>>(q_w, q_b, k_w, k_b, v_w, v_b, g_w, g_b);
    // 6. QKVG = h @ Wp^T + bp  (into g_X)
    hmma_gemm<false><<<dim3(2, gm), blk>>>(PIN, PIN_D, Wp, bp, QKVG, QKVG_N, QKVG_N, HID);
    // 7. attention -> PIN[:, 256:320]
    attn_kernel<<<BSZ, blk>>>();
    // 8. PH = relu(PIN @ p1_w^T + p1_b)  (K=320 = 10 chunks)
    hmma_gemm<true ><<<dim3(2, gm), blk>>>(PIN, PIN_D, p1_w, p1_b, PH, HID, HID, PIN_D);
    // 9. logits = PH @ p2_w^T + p2_b
    hmma_gemm<false><<<dim3(1, gm), blk>>>(PH, HID, p2_w, p2_b, logits, NACT, NACT, HID);
}

// round 17
// speedup vs baseline: 2.1089x; 1.6766x over previous
#include <cuda_runtime.h>
#include <cuda_bf16.h>
#include <cstdint>

#define BSZ   2048
#define NAG   32
#define NROWS (BSZ*NAG)     // 65536
#define IND   256
#define HID   256
#define NHD   4
#define HDIM  16
#define CVD   16
#define QKVG_N 196
#define PIN_D 320
#define NACT  20
#define TOPK_K 8
#define NEGV  (-1e10f)

// ---------------- scratch ----------------
__device__ float g_X   [(size_t)NROWS * HID];     // relu(fc1); reused as QKVG
__device__ float g_GI  [(size_t)NROWS * 768];     // reused as PH
__device__ float g_GH  [(size_t)NROWS * 768];
__device__ float g_PIN [(size_t)NROWS * PIN_D];
__device__ float g_Wp  [QKVG_N * HID];
__device__ float g_bp  [QKVG_N];

// ---------------- mma.sync bf16 helpers (base-target sm_80+) ----------------
__device__ __forceinline__ void mma_bf16(float* c, const uint32_t* a, const uint32_t* b) {
    asm volatile("mma.sync.aligned.m16n8k16.row.col.f32.bf16.bf16.f32 "
                 "{%0,%1,%2,%3}, {%4,%5,%6,%7}, {%8,%9}, {%0,%1,%2,%3};"
                 : "+f"(c[0]), "+f"(c[1]), "+f"(c[2]), "+f"(c[3])
                 : "r"(a[0]), "r"(a[1]), "r"(a[2]), "r"(a[3]),
                   "r"(b[0]), "r"(b[1]));
}
__device__ __forceinline__ uint32_t pkbf(__nv_bfloat16 a, __nv_bfloat16 b) {
    return (uint32_t)__bfloat16_as_ushort(a) | ((uint32_t)__bfloat16_as_ushort(b) << 16);
}

// ---------------- split-bf16 HMMA GEMM: C = A[M,K] @ B[N,K]^T + bias --------
// fp32-class accuracy via 3-term bf16 emulation: a=ah+al, b=bh+bl,
// acc += ah*bh + ah*bl + al*bh  (al*bl ~2^-18, neglected). fp32 accumulate.
// CTA: 256 thr, tile 128(M) x 128(N), K-chunks of 32 (= 2 k16 blocks).
// Warp grid 4(M) x 2(N); warp tile 32 x 64 = 2 m-tiles x 8 n-tiles m16n8k16.
// SMEM 32 KB static: fragment-permuted, pre-split bf16x2:
//   As_hi/As_lo: [kb 0..1][tm 0..7][lane][reg 0..3]  (8 KB each)
//   Bs_hi/Bs_lo: [kb 0..1][nt 0..15][lane][reg 0..1] (8 KB each)
// m16n8k16 fragment maps (k8 map proven in R11/R15; k16 = hi x khalf regs):
//   A: a0=(g, kp)       a1=(g+8, kp)       kp = k-pair 2c,2c+1 of khalf 0
//      a2=(g, kp+8)     a3=(g+8, kp+8)     (khalf 1)      lane = g*4+c
//   B: b0=(k=2c.., n=g) khalf0, b1 khalf1
//   C: c0=(g,2c) c1=(g,2c+1) c2=(g+8,2c) c3=(g+8,2c+1)
template<bool RELU>
__global__ void __launch_bounds__(256, 2)
hmma_gemm(const float* __restrict__ A, int lda,
          const float* __restrict__ B,            // [N,K] row-major
          const float* __restrict__ bias,
          float* __restrict__ C, int ldc,
          int Nfull, int K)
{
    __shared__ uint32_t As_hi[2 * 8 * 32 * 4];   // 8 KB
    __shared__ uint32_t As_lo[2 * 8 * 32 * 4];   // 8 KB
    __shared__ uint32_t Bs_hi[2 * 16 * 32 * 2];  // 8 KB
    __shared__ uint32_t Bs_lo[2 * 16 * 32 * 2];  // 8 KB

    const int tid  = threadIdx.x;
    const int wid  = tid >> 5;
    const int lane = tid & 31;
    const int wm   = wid >> 1;       // 0..3  (M)
    const int wn   = wid & 1;        // 0..1  (N)
    const int m0   = blockIdx.y * 128;
    const int n0   = blockIdx.x * 128;

    float acc[2][8][4];
#pragma unroll
    for (int mt = 0; mt < 2; mt++)
#pragma unroll
        for (int j = 0; j < 8; j++)
#pragma unroll
            for (int r = 0; r < 4; r++) acc[mt][j][r] = 0.f;

    const int nkc = K >> 5;   // chunks of 32 (all K here are multiples of 32)

    for (int ch = 0; ch < nkc; ch++) {
        const int k0 = ch << 5;
        __syncthreads();
        // ---- cooperative load: split hi/lo bf16, fragment-permute ----
#pragma unroll
        for (int it = 0; it < 4; it++) {
            int slot  = it * 256 + tid;          // 0..1023
            int row   = slot >> 3;               // 0..127
            int k     = (slot & 7) << 2;         // 0,4,..,28
            int kb    = k >> 4;                  // 0..1 (k16 block)
            int kk    = k & 15;
            int khalf = kk >> 3;                 // 0..1
            int cpair = (kk & 7) >> 1;           // 0 or 2; float4 covers cpair, cpair+1

            // A (m0+row, k0+k..+3)
            {
                float4 av = *(const float4*)(A + (size_t)(m0 + row) * lda + k0 + k);
                __nv_bfloat16 hx = __float2bfloat16(av.x), hy = __float2bfloat16(av.y);
                __nv_bfloat16 hz = __float2bfloat16(av.z), hw = __float2bfloat16(av.w);
                __nv_bfloat16 lx = __float2bfloat16(av.x - __bfloat162float(hx));
                __nv_bfloat16 ly = __float2bfloat16(av.y - __bfloat162float(hy));
                __nv_bfloat16 lz = __float2bfloat16(av.z - __bfloat162float(hz));
                __nv_bfloat16 lw = __float2bfloat16(av.w - __bfloat162float(hw));
                int tm  = row >> 4;
                int g   = row & 7;
                int hi  = (row >> 3) & 1;
                int reg = hi + 2 * khalf;
                int base = ((kb * 8 + tm) * 32) * 4 + reg;
                As_hi[base + (g * 4 + cpair) * 4]     = pkbf(hx, hy);
                As_hi[base + (g * 4 + cpair + 1) * 4] = pkbf(hz, hw);
                As_lo[base + (g * 4 + cpair) * 4]     = pkbf(lx, ly);
                As_lo[base + (g * 4 + cpair + 1) * 4] = pkbf(lz, lw);
            }
            // B (n0+row, k0+k..+3)
            {
                float4 bv = make_float4(0.f, 0.f, 0.f, 0.f);
                if (n0 + row < Nfull)
                    bv = *(const float4*)(B + (size_t)(n0 + row) * K + k0 + k);
                __nv_bfloat16 hx = __float2bfloat16(bv.x), hy = __float2bfloat16(bv.y);
                __nv_bfloat16 hz = __float2bfloat16(bv.z), hw = __float2bfloat16(bv.w);
                __nv_bfloat16 lx = __float2bfloat16(bv.x - __bfloat162float(hx));
                __nv_bfloat16 ly = __float2bfloat16(bv.y - __bfloat162float(hy));
                __nv_bfloat16 lz = __float2bfloat16(bv.z - __bfloat162float(hz));
                __nv_bfloat16 lw = __float2bfloat16(bv.w - __bfloat162float(hw));
                int nt  = row >> 3;
                int g   = row & 7;
                int base = ((kb * 16 + nt) * 32) * 2 + khalf;
                Bs_hi[base + (g * 4 + cpair) * 2]     = pkbf(hx, hy);
                Bs_hi[base + (g * 4 + cpair + 1) * 2] = pkbf(hz, hw);
                Bs_lo[base + (g * 4 + cpair) * 2]     = pkbf(lx, ly);
                Bs_lo[base + (g * 4 + cpair + 1) * 2] = pkbf(lz, lw);
            }
        }
        __syncthreads();
        // ---- 2 k16-steps, 3-term split, all operands pre-split ----
#pragma unroll
        for (int kb = 0; kb < 2; kb++) {
            uint32_t ah[2][4], al[2][4];
#pragma unroll
            for (int mt = 0; mt < 2; mt++) {
                int off = ((kb * 8 + wm * 2 + mt) * 32 + lane) * 4;
                uint4 vh = *(const uint4*)(As_hi + off);
                ah[mt][0] = vh.x; ah[mt][1] = vh.y; ah[mt][2] = vh.z; ah[mt][3] = vh.w;
                uint4 vl = *(const uint4*)(As_lo + off);
                al[mt][0] = vl.x; al[mt][1] = vl.y; al[mt][2] = vl.z; al[mt][3] = vl.w;
            }
#pragma unroll
            for (int j = 0; j < 8; j++) {
                int boff = ((kb * 16 + wn * 8 + j) * 32 + lane) * 2;
                uint2 vbh = *(const uint2*)(Bs_hi + boff);
                uint2 vbl = *(const uint2*)(Bs_lo + boff);
                uint32_t bh[2] = {vbh.x, vbh.y};
                uint32_t bl[2] = {vbl.x, vbl.y};
#pragma unroll
                for (int mt = 0; mt < 2; mt++) {
                    mma_bf16(acc[mt][j], ah[mt], bh);
                    mma_bf16(acc[mt][j], ah[mt], bl);
                    mma_bf16(acc[mt][j], al[mt], bh);
                }
            }
        }
    }

    // ---- epilogue: bias (+relu), direct float2 stores ----
    const int g = lane >> 2;
    const int c = lane & 3;
#pragma unroll
    for (int mt = 0; mt < 2; mt++) {
#pragma unroll
        for (int j = 0; j < 8; j++) {
            int col = n0 + wn * 64 + j * 8 + c * 2;
            if (col >= Nfull) continue;
            float b0 = __ldg(bias + col);
            float b1 = __ldg(bias + col + 1);
            int r0 = m0 + wm * 32 + mt * 16 + g;
            float v0 = acc[mt][j][0] + b0;
            float v1 = acc[mt][j][1] + b1;
            float v2 = acc[mt][j][2] + b0;
            float v3 = acc[mt][j][3] + b1;
            if (RELU) {
                v0 = fmaxf(v0, 0.f); v1 = fmaxf(v1, 0.f);
                v2 = fmaxf(v2, 0.f); v3 = fmaxf(v3, 0.f);
            }
            *(float2*)(C + (size_t)r0 * ldc + col)       = make_float2(v0, v1);
            *(float2*)(C + (size_t)(r0 + 8) * ldc + col) = make_float2(v2, v3);
        }
    }
}

// ---------------- GRU elementwise ----------------
__global__ void gru_kernel(const float* __restrict__ h_in,
                           float* __restrict__ h_out_tail)
{
    int idx = blockIdx.x * blockDim.x + threadIdx.x;
    if (idx >= NROWS * HID) return;
    int row = idx >> 8;
    int j   = idx & 255;
    size_t base = (size_t)row * 768;
    float gir = g_GI[base + j],       ghr = g_GH[base + j];
    float giz = g_GI[base + 256 + j], ghz = g_GH[base + 256 + j];
    float gin = g_GI[base + 512 + j], ghn = g_GH[base + 512 + j];
    float hp = h_in[idx];
    float r = 1.f / (1.f + __expf(-(gir + ghr)));
    float z = 1.f / (1.f + __expf(-(giz + ghz)));
    float n = tanhf(gin + r * ghn);
    float h = (1.f - z) * n + z * hp;
    g_PIN[(size_t)row * PIN_D + j] = h;
    h_out_tail[idx] = h;
}

// ---------------- pack q/k/v/g weights ----------------
__global__ void pack_qkvg(const float* __restrict__ qw, const float* __restrict__ qb,
                          const float* __restrict__ kw, const float* __restrict__ kb,
                          const float* __restrict__ vw, const float* __restrict__ vb,
                          const float* __restrict__ gw, const float* __restrict__ gb)
{
    int n = blockIdx.x;
    const float* src; const float* sb; int r;
    if      (n < 64)  { src = qw; sb = qb; r = n;       }
    else if (n < 128) { src = kw; sb = kb; r = n - 64;  }
    else if (n < 192) { src = vw; sb = vb; r = n - 128; }
    else              { src = gw; sb = gb; r = n - 192; }
    for (int k = threadIdx.x; k < HID; k += blockDim.x)
        g_Wp[n * HID + k] = src[r * HID + k];
    if (threadIdx.x == 0) g_bp[n] = sb[r];
}

// ---------------- attention per batch element ----------------
__global__ void __launch_bounds__(256) attn_kernel()
{
    __shared__ float sq[NAG][NHD * HDIM];
    __shared__ float sk[NAG][NHD * HDIM];
    __shared__ float sv[NAG][NHD * CVD];
    __shared__ float sg[NAG][NHD];
    __shared__ float ss[NAG][NHD][NAG];

    int b   = blockIdx.x;
    int tid = threadIdx.x;

    for (int idx = tid; idx < NAG * QKVG_N; idx += 256) {
        int a = idx / QKVG_N, c = idx % QKVG_N;
        float v = g_X[((size_t)(b * NAG + a)) * QKVG_N + c];
        if      (c < 64)  sq[a][c]       = v;
        else if (c < 128) sk[a][c - 64]  = v;
        else if (c < 192) sv[a][c - 128] = v;
        else              sg[a][c - 192] = v;
    }
    __syncthreads();

    for (int idx = tid; idx < NAG * NHD * NAG; idx += 256) {
        int qa = idx >> 7;
        int h  = (idx >> 5) & 3;
        int ka = idx & 31;
        float s;
        if (qa == ka) s = NEGV;
        else {
            s = 0.f;
#pragma unroll
            for (int d = 0; d < HDIM; d++)
                s += sq[qa][h * HDIM + d] * sk[ka][h * HDIM + d];
            s *= 0.25f;
        }
        ss[qa][h][ka] = s;
    }
    __syncthreads();

    if (tid < NAG * NHD) {
        int qa = tid >> 2, h = tid & 3;
        float* s = ss[qa][h];
        unsigned kept = 0u;
        float m = -3e38f;
#pragma unroll
        for (int t = 0; t < TOPK_K; t++) {
            float best = -3e38f; int bi = 0;
            for (int k = 0; k < NAG; k++)
                if (!((kept >> k) & 1u) && s[k] > best) { best = s[k]; bi = k; }
            kept |= 1u << bi;
            if (t == 0) m = best;
        }
        float denom = 0.f;
        for (int k = 0; k < NAG; k++) {
            float e = ((kept >> k) & 1u) ? __expf(s[k] - m) : 0.f;
            s[k] = e;
            denom += e;
        }
        float inv = 1.f / denom;
        for (int k = 0; k < NAG; k++) s[k] *= inv;
    }
    __syncthreads();

    for (int idx = tid; idx < NAG * NHD * CVD; idx += 256) {
        int qa = idx >> 6;
        int h  = (idx >> 4) & 3;
        int c  = idx & 15;
        float acc = 0.f;
#pragma unroll
        for (int ka = 0; ka < NAG; ka++)
            acc += ss[qa][h][ka] * sv[ka][h * CVD + c];
        float gate = 1.f / (1.f + __expf(-sg[qa][h]));
        g_PIN[((size_t)(b * NAG + qa)) * PIN_D + HID + h * CVD + c] = acc * gate;
    }
}

// ---------------- launch ----------------
extern "C" void kernel_launch(void* const* d_in, const int* in_sizes, int n_in,
                              void* d_out, int out_size)
{
    const float* inputs   = (const float*)d_in[0];
    const float* hidden   = (const float*)d_in[1];
    const float* fc1_w    = (const float*)d_in[2];
    const float* fc1_b    = (const float*)d_in[3];
    const float* gru_w_ih = (const float*)d_in[4];
    const float* gru_w_hh = (const float*)d_in[5];
    const float* gru_b_ih = (const float*)d_in[6];
    const float* gru_b_hh = (const float*)d_in[7];
    const float* q_w = (const float*)d_in[8];
    const float* q_b = (const float*)d_in[9];
    const float* k_w = (const float*)d_in[10];
    const float* k_b = (const float*)d_in[11];
    const float* v_w = (const float*)d_in[12];
    const float* v_b = (const float*)d_in[13];
    const float* g_w = (const float*)d_in[14];
    const float* g_b = (const float*)d_in[15];
    const float* p1_w = (const float*)d_in[16];
    const float* p1_b = (const float*)d_in[17];
    const float* p2_w = (const float*)d_in[18];
    const float* p2_b = (const float*)d_in[19];

    float* out    = (float*)d_out;
    float* logits = out;
    float* h_out  = out + (size_t)NROWS * NACT;

    float *X, *GI, *GH, *PIN, *Wp, *bp;
    cudaGetSymbolAddress((void**)&X,    g_X);
    cudaGetSymbolAddress((void**)&GI,   g_GI);
    cudaGetSymbolAddress((void**)&GH,   g_GH);
    cudaGetSymbolAddress((void**)&PIN,  g_PIN);
    cudaGetSymbolAddress((void**)&Wp,   g_Wp);
    cudaGetSymbolAddress((void**)&bp,   g_bp);
    float* QKVG = X;
    float* PH   = GI;

    const dim3 blk(256);
    const int gm = NROWS / 128;   // 512

    // 1. X = relu(inputs @ fc1_w^T + fc1_b)
    hmma_gemm<true ><<<dim3(2, gm), blk>>>(inputs, IND, fc1_w, fc1_b, X, HID, HID, IND);
    // 2. GI = X @ W_ih^T + b_ih
    hmma_gemm<false><<<dim3(6, gm), blk>>>(X, HID, gru_w_ih, gru_b_ih, GI, 768, 768, HID);
    // 3. GH = hidden @ W_hh^T + b_hh
    hmma_gemm<false><<<dim3(6, gm), blk>>>(hidden, HID, gru_w_hh, gru_b_hh, GH, 768, 768, HID);
    // 4. GRU -> h (PIN[:, :256] + output tail)
    gru_kernel<<<(NROWS * HID) / 256, blk>>>(hidden, h_out);
    // 5. pack q/k/v/g weights
    pack_qkvg<<<QKVG_N, blk>>>(q_w, q_b, k_w, k_b, v_w, v_b, g_w, g_b);
    // 6. QKVG = h @ Wp^T + bp  (into g_X)
    hmma_gemm<false><<<dim3(2, gm), blk>>>(PIN, PIN_D, Wp, bp, QKVG, QKVG_N, QKVG_N, HID);
    // 7. attention -> PIN[:, 256:320]
    attn_kernel<<<BSZ, blk>>>();
    // 8. PH = relu(PIN @ p1_w^T + p1_b)  (K=320 = 10 chunks)
    hmma_gemm<true ><<<dim3(2, gm), blk>>>(PIN, PIN_D, p1_w, p1_b, PH, HID, HID, PIN_D);
    // 9. logits = PH @ p2_w^T + p2_b
    hmma_gemm<false><<<dim3(1, gm), blk>>>(PH, HID, p2_w, p2_b, logits, NACT, NACT, HID);
}